// round 3
// baseline (speedup 1.0000x reference)
#include <cuda_runtime.h>
#include <cuda_bf16.h>

// QuantumFeatureMap closed form: t_q = cos(1.57*x_q), outputs are subset products:
//   Z0=t1t2t3  Z1=t0t1  Z2=t0t1t2  Z3=t0t1t2t3
//   Z0Z1=t0t2t3  Z0Z2=t0t3  Z0Z3=t0  Z1Z2=t2  Z1Z3=t2t3  Z2Z3=t3
//
// R2 -> R3: 4 rows/thread (MLP=4), float2 shared stores, same coalesced
// float4 global store epilogue. Grid 1024 x 256.

#define QFM_ALPHA 1.57f
#define QFM_BLOCK 256
#define QFM_RPT   4
#define QFM_ROWS  (QFM_BLOCK * QFM_RPT)   // 1024 rows per block

__global__ void __launch_bounds__(QFM_BLOCK)
qfm_kernel(const float4* __restrict__ x, float4* __restrict__ out)
{
    __shared__ __align__(16) float s[QFM_ROWS * 10];   // 40960 B

    const int tid  = threadIdx.x;
    const int base = blockIdx.x * QFM_ROWS;

    // Front-batched independent loads: 4 coalesced LDG.128 in flight.
    float4 v[QFM_RPT];
    #pragma unroll
    for (int k = 0; k < QFM_RPT; k++)
        v[k] = x[base + tid + k * QFM_BLOCK];

    float2* s2 = (float2*)s;

    #pragma unroll
    for (int k = 0; k < QFM_RPT; k++) {
        float t0 = __cosf(QFM_ALPHA * v[k].x);
        float t1 = __cosf(QFM_ALPHA * v[k].y);
        float t2 = __cosf(QFM_ALPHA * v[k].z);
        float t3 = __cosf(QFM_ALPHA * v[k].w);

        float t01 = t0 * t1;
        float t23 = t2 * t3;

        // Row-local index within block
        const int r = tid + k * QFM_BLOCK;
        float2* p = s2 + r * 5;               // 40B per row, 8B aligned
        p[0] = make_float2(t1 * t23, t01);    // out0, out1
        p[1] = make_float2(t01 * t2, t01 * t23); // out2, out3
        p[2] = make_float2(t0 * t23, t0 * t3);   // out4, out5
        p[3] = make_float2(t0, t2);              // out6, out7
        p[4] = make_float2(t23, t3);             // out8, out9
    }

    __syncthreads();

    // Block output: QFM_ROWS * 10 floats = 10240 floats = 2560 float4.
    // Fully coalesced STG.128 (each warp writes contiguous 512B per instr).
    const float4* s4 = (const float4*)s;
    float4* o = out + (size_t)blockIdx.x * (QFM_ROWS * 10 / 4);

    #pragma unroll
    for (int i = 0; i < QFM_ROWS * 10 / 4 / QFM_BLOCK; i++)
        o[tid + i * QFM_BLOCK] = s4[tid + i * QFM_BLOCK];
}

extern "C" void kernel_launch(void* const* d_in, const int* in_sizes, int n_in,
                              void* d_out, int out_size)
{
    const float4* x = (const float4*)d_in[0];
    float4* out = (float4*)d_out;

    const int n_rows = in_sizes[0] / 4;            // [B,4] float32 -> 1048576
    const int grid = n_rows / QFM_ROWS;            // 1024 blocks

    qfm_kernel<<<grid, QFM_BLOCK>>>(x, out);
}